// round 10
// baseline (speedup 1.0000x reference)
#include <cuda_runtime.h>
#include <cuda_fp16.h>
#include <cstdint>

#define B_ 2
#define N_ 65536
#define H_ 8
#define TILES_PER_CTA 8
#define NCHUNK 64

// ---- smem layout (byte offsets); every pitch = 16 mod 128 bytes ----
#define PWB   528                   // W pitch: 264 halves
#define SW_B  0                     // W [n][k] fp16: n 0..63 = W_xs (fused), 64..127 = W_fx
#define PXB   144                   // x chunk pitch: 72 halves
#define SX_B  67584                 // x chunk fp16 18432 B ; alias sFxT [d][tok] p272 ; alias Wsl fp32 scratch
#define PPB   144
#define SP_B  86016                 // w transposed [s][tok] p272
#define PTB   272
#define SRED_B 113664               // [0..63] fused slice bias (float) ; +1024: row-sum exchange (256 floats)
#define SBIAS_B 115712              // 128 floats: 0-63 bx, 64-127 bfx
#define SMEM_BYTES 116224

__device__ float g_A[B_ * H_ * 64 * 64];
__device__ float g_norm[B_ * H_ * 64];

__device__ __forceinline__ uint32_t smem_u32(const void* p) {
    uint32_t a;
    asm("{ .reg .u64 t; cvta.to.shared.u64 t, %1; cvt.u32.u64 %0, t; }" : "=r"(a) : "l"(p));
    return a;
}
__device__ __forceinline__ uint32_t f22h2(float a, float b) {
    __half2 h = __floats2half2_rn(a, b);
    return *reinterpret_cast<uint32_t*>(&h);
}
__device__ __forceinline__ void mma16(float* d, const unsigned* a, unsigned b0, unsigned b1) {
    asm volatile("mma.sync.aligned.m16n8k16.row.col.f32.f16.f16.f32 "
                 "{%0,%1,%2,%3},{%4,%5,%6,%7},{%8,%9},{%0,%1,%2,%3};"
                 : "+f"(d[0]), "+f"(d[1]), "+f"(d[2]), "+f"(d[3])
                 : "r"(a[0]), "r"(a[1]), "r"(a[2]), "r"(a[3]), "r"(b0), "r"(b1));
}
__device__ __forceinline__ void ldsm4(uint32_t addr, unsigned* r) {
    asm volatile("ldmatrix.sync.aligned.m8n8.x4.shared.b16 {%0,%1,%2,%3}, [%4];"
                 : "=r"(r[0]), "=r"(r[1]), "=r"(r[2]), "=r"(r[3]) : "r"(addr));
}

__global__ void k_zero() {
    int i = blockIdx.x * 256 + threadIdx.x;
    if (i < B_ * H_ * 64 * 64) g_A[i] = 0.0f;
    if (i < B_ * H_ * 64)      g_norm[i] = 0.0f;
}

__global__ __launch_bounds__(512, 1)
void k_fused(const float* __restrict__ x,
             const float* __restrict__ Wx,  const float* __restrict__ bx,
             const float* __restrict__ Wfx, const float* __restrict__ bfx,
             const float* __restrict__ Wsl, const float* __restrict__ bsl,
             const float* __restrict__ temp)
{
    extern __shared__ char smb[];
    __half* sWh   = (__half*)(smb + SW_B);
    float*  sWslF = (float*)(smb + SX_B);          // fp32 scratch, pitch 68 (staging only)
    float*  sBiasS = (float*)(smb + SRED_B);       // fused slice bias [64]
    float*  sRedS  = (float*)(smb + SRED_B + 1024);// row partial sums [256]
    float*  sBias  = (float*)(smb + SBIAS_B);

    const uint32_t sb   = smem_u32(smb);
    const uint32_t sXu  = sb + SX_B;
    const uint32_t sWu  = sb + SW_B;
    const uint32_t sPu  = sb + SP_B;

    const int tid  = threadIdx.x;
    const int b    = blockIdx.z, h = blockIdx.y;
    const int lane = tid & 31, wid = tid >> 5;
    const int g    = lane >> 2, t = lane & 3;

    // main GEMM roles: 4 m-warps x 4 n-warps
    const int tokBase = (wid >> 2) * 32;
    const int nw      = wid & 3;
    const int colBase = nw * 32;
    // agg roles: 4 (s) x 4 (d)
    const int sB3 = (wid >> 2) * 16, dB3 = (wid & 3) * 16;

    // ---- phase a: stage W_fx (sW cols 64-127), Wsl fp32 scratch, biases ----
    {
        const float4* Wfx4 = (const float4*)Wfx;
        #pragma unroll
        for (int it = 0; it < 8; it++) {
            int f = tid + it * 512;            // 0..4095 over 256k x 16 float4
            int k = f >> 4, q = f & 15;
            float4 v = Wfx4[k * 128 + h * 16 + q];
            int n = 64 + 4 * q;
            sWh[(n + 0) * 264 + k] = __float2half_rn(v.x);
            sWh[(n + 1) * 264 + k] = __float2half_rn(v.y);
            sWh[(n + 2) * 264 + k] = __float2half_rn(v.z);
            sWh[(n + 3) * 264 + k] = __float2half_rn(v.w);
        }
        #pragma unroll
        for (int it = 0; it < 8; it++) {
            int f = tid + it * 512;            // 0..4095 = 64d x 64s
            int d = f >> 6, s = f & 63;
            sWslF[d * 68 + s] = Wsl[f];
        }
        if (tid < 128)
            sBias[tid] = (tid < 64) ? bx[h * 64 + tid] : bfx[h * 64 + (tid - 64)];
    }
    __syncthreads();

    // ---- phase b: W_xs = W_x(head) @ Wsl -> sW cols 0-63 ; fused slice bias ----
    {
        const int k = tid >> 1, sh = (tid & 1) * 32;
        const float4* wrow = (const float4*)(Wx + (size_t)k * 512 + h * 64);
        float2 a2[16];
        #pragma unroll
        for (int j = 0; j < 16; j++) a2[j] = make_float2(0.f, 0.f);
        #pragma unroll 4
        for (int p4 = 0; p4 < 16; p4++) {
            float4 wv = wrow[p4];
            const int d0 = p4 * 4;
            #pragma unroll
            for (int dd = 0; dd < 4; dd++) {
                float wsc = (dd == 0) ? wv.x : (dd == 1) ? wv.y : (dd == 2) ? wv.z : wv.w;
                const float2* r = (const float2*)&sWslF[(d0 + dd) * 68 + sh];
                #pragma unroll
                for (int j = 0; j < 16; j++) {
                    float2 wl = r[j];
                    a2[j].x += wsc * wl.x;
                    a2[j].y += wsc * wl.y;
                }
            }
        }
        #pragma unroll
        for (int j = 0; j < 16; j++) {
            int s = sh + 2 * j;
            sWh[(s + 0) * 264 + k] = __float2half_rn(a2[j].x);
            sWh[(s + 1) * 264 + k] = __float2half_rn(a2[j].y);
        }
        if (tid < 64) {
            float acc = bsl[tid];
            #pragma unroll 8
            for (int d = 0; d < 64; d++) acc += sBias[d] * sWslF[d * 68 + tid];
            sBiasS[tid] = acc;
        }
    }
    __syncthreads();

    float tv = fminf(fmaxf(temp[h], 0.5f), 5.0f);
    const float invT = 1.0f / tv;
    float bSr[8];
    #pragma unroll
    for (int j = 0; j < 4; j++)
        #pragma unroll
        for (int e = 0; e < 2; e++) bSr[2 * j + e] = sBiasS[colBase % 64 + 8 * j + 2 * t + e];

    // ldmatrix bases
    const int lr = lane & 15, lc = lane >> 4;
    const uint32_t aA0 = sXu + (uint32_t)(tokBase + lr) * PXB + lc * 16;
    const uint32_t bB0 = sWu + (uint32_t)(colBase + lr) * PWB + lc * 16;
    const uint32_t wA0 = sPu + (uint32_t)(sB3 + lr) * PTB + lc * 16;
    const uint32_t fB0 = sXu + (uint32_t)(dB3 + lr) * PTB + lc * 16;

    float aggAcc[2][4];
    #pragma unroll
    for (int j = 0; j < 2; j++)
        #pragma unroll
        for (int e = 0; e < 4; e++) aggAcc[j][e] = 0.0f;
    float na[8];
    #pragma unroll
    for (int i = 0; i < 8; i++) na[i] = 0.0f;

    const float4* xg4 = (const float4*)x + (size_t)b * (size_t)N_ * 64;
    const int cTok = tid >> 2, cQ = tid & 3;
    const uint32_t stsAddr = sXu + (uint32_t)cTok * PXB + cQ * 32;

    float4 xr[4];
    {
        const float4* src = xg4 + (size_t)((blockIdx.x * TILES_PER_CTA) * 128 + cTok) * 64 + cQ * 4;
        #pragma unroll
        for (int i = 0; i < 4; i++) xr[i] = src[i];
    }

    for (int tnum = 0; tnum < TILES_PER_CTA; tnum++) {
        const int n0 = (blockIdx.x * TILES_PER_CTA + tnum) * 128;
        __syncthreads();   // epilogue reads of aliased regions done

        float acc[2][4][4];
        #pragma unroll
        for (int i = 0; i < 2; i++)
            #pragma unroll
            for (int j = 0; j < 4; j++)
                #pragma unroll
                for (int e = 0; e < 4; e++) acc[i][j][e] = 0.0f;

        const float4* srcRow = xg4 + (size_t)(n0 + cTok) * 64 + cQ * 4;

        for (int c = 0; c < 4; c++) {
            {
                uint4 u0, u1;
                u0.x = f22h2(xr[0].x, xr[0].y); u0.y = f22h2(xr[0].z, xr[0].w);
                u0.z = f22h2(xr[1].x, xr[1].y); u0.w = f22h2(xr[1].z, xr[1].w);
                u1.x = f22h2(xr[2].x, xr[2].y); u1.y = f22h2(xr[2].z, xr[2].w);
                u1.z = f22h2(xr[3].x, xr[3].y); u1.w = f22h2(xr[3].z, xr[3].w);
                *(uint4*)(smb + (stsAddr - sb))      = u0;
                *(uint4*)(smb + (stsAddr - sb) + 16) = u1;
            }
            if (c < 3) {
                const float4* src = srcRow + (c + 1) * 16;
                #pragma unroll
                for (int i = 0; i < 4; i++) xr[i] = src[i];
            }
            __syncthreads();

            const uint32_t kB = bB0 + (uint32_t)c * 128;
            #pragma unroll
            for (int ks = 0; ks < 4; ks++) {
                unsigned a0[4], a1[4], p0[4], p1[4];
                ldsm4(aA0 + ks * 32, a0);
                ldsm4(aA0 + 16 * PXB + ks * 32, a1);
                ldsm4(kB + ks * 32, p0);
                ldsm4(kB + 16 * PWB + ks * 32, p1);
                mma16(acc[0][0], a0, p0[0], p0[2]);
                mma16(acc[0][1], a0, p0[1], p0[3]);
                mma16(acc[0][2], a0, p1[0], p1[2]);
                mma16(acc[0][3], a0, p1[1], p1[3]);
                mma16(acc[1][0], a1, p0[0], p0[2]);
                mma16(acc[1][1], a1, p0[1], p0[3]);
                mma16(acc[1][2], a1, p1[0], p1[2]);
                mma16(acc[1][3], a1, p1[1], p1[3]);
            }
            __syncthreads();
        }

        // prefetch next tile's chunk 0 under the epilogue
        if (tnum + 1 < TILES_PER_CTA) {
            const float4* src = xg4 + (size_t)(n0 + 128 + cTok) * 64 + cQ * 4;
            #pragma unroll
            for (int i = 0; i < 4; i++) xr[i] = src[i];
        }

        // ---- epilogue: nw<2 softmax on accumulators; nw>=2 fx stores ----
        float wv[4][8];
        float osum[4];
        if (nw < 2) {
            #pragma unroll
            for (int i = 0; i < 2; i++)
                #pragma unroll
                for (int j = 0; j < 4; j++)
                    #pragma unroll
                    for (int e = 0; e < 2; e++) {
                        wv[2 * i + 0][2 * j + e] = __expf((acc[i][j][e]     + bSr[2 * j + e]) * invT);
                        wv[2 * i + 1][2 * j + e] = __expf((acc[i][j][2 + e] + bSr[2 * j + e]) * invT);
                    }
            #pragma unroll
            for (int rr = 0; rr < 4; rr++) {
                float s = 0.0f;
                #pragma unroll
                for (int i = 0; i < 8; i++) s += wv[rr][i];
                s += __shfl_xor_sync(0xffffffffu, s, 1);
                s += __shfl_xor_sync(0xffffffffu, s, 2);
                osum[rr] = s;
            }
            if (t == 0) {
                #pragma unroll
                for (int rr = 0; rr < 4; rr++) {
                    int row = tokBase + 16 * (rr >> 1) + g + 8 * (rr & 1);
                    sRedS[nw * 128 + row] = osum[rr];
                }
            }
        } else {
            #pragma unroll
            for (int i = 0; i < 2; i++)
                #pragma unroll
                for (int j = 0; j < 4; j++) {
                    int row = tokBase + 16 * i + g;
                    #pragma unroll
                    for (int e = 0; e < 2; e++) {
                        int d = (colBase - 64) + 8 * j + 2 * t + e;
                        float bf = sBias[64 + d];
                        *(__half*)(smb + SX_B + d * PTB + row * 2) =
                            __float2half_rn(acc[i][j][e] + bf);
                        *(__half*)(smb + SX_B + d * PTB + (row + 8) * 2) =
                            __float2half_rn(acc[i][j][2 + e] + bf);
                    }
                }
        }
        __syncthreads();

        if (nw < 2) {
            #pragma unroll
            for (int rr = 0; rr < 4; rr++) {
                int row = tokBase + 16 * (rr >> 1) + g + 8 * (rr & 1);
                float inv = __frcp_rn(osum[rr] + sRedS[(1 ^ nw) * 128 + row]);
                #pragma unroll
                for (int j = 0; j < 4; j++)
                    #pragma unroll
                    for (int e = 0; e < 2; e++) {
                        int s = colBase + 8 * j + 2 * t + e;
                        __half hv = __float2half_rn(wv[rr][2 * j + e] * inv);
                        *(__half*)(smb + SP_B + s * PTB + row * 2) = hv;
                        na[2 * j + e] += __half2float(hv);
                    }
            }
        }
        __syncthreads();

        // ---- aggregation: A[s,d] += w^T @ fx, K = 128 tokens ----
        #pragma unroll
        for (int ks = 0; ks < 8; ks++) {
            unsigned a[4], bb[4];
            ldsm4(wA0 + ks * 32, a);
            ldsm4(fB0 + ks * 32, bb);
            mma16(aggAcc[0], a, bb[0], bb[2]);
            mma16(aggAcc[1], a, bb[1], bb[3]);
        }
    }

    // ---- flush ----
    float* gA = g_A + (size_t)((b * H_ + h) * 64) * 64;
    #pragma unroll
    for (int j = 0; j < 2; j++) {
        int d0 = dB3 + 8 * j + 2 * t;
        atomicAdd(&gA[(sB3 + g) * 64 + d0],         aggAcc[j][0]);
        atomicAdd(&gA[(sB3 + g) * 64 + d0 + 1],     aggAcc[j][1]);
        atomicAdd(&gA[(sB3 + g + 8) * 64 + d0],     aggAcc[j][2]);
        atomicAdd(&gA[(sB3 + g + 8) * 64 + d0 + 1], aggAcc[j][3]);
    }
    if (nw < 2) {
        #pragma unroll
        for (int i = 0; i < 8; i++) {
            float v = na[i];
            v += __shfl_xor_sync(0xffffffffu, v, 4);
            v += __shfl_xor_sync(0xffffffffu, v, 8);
            v += __shfl_xor_sync(0xffffffffu, v, 16);
            if (lane < 4)
                atomicAdd(&g_norm[(b * H_ + h) * 64 + colBase + 8 * (i >> 1) + 2 * t + (i & 1)], v);
        }
    }
}

__global__ void k_final(float* __restrict__ out) {
    int i = blockIdx.x * 256 + threadIdx.x;
    out[i] = g_A[i] / (g_norm[i >> 6] + 0.01f);
}

extern "C" void kernel_launch(void* const* d_in, const int* in_sizes, int n_in,
                              void* d_out, int out_size) {
    const float* x    = (const float*)d_in[0];
    const float* Wx   = (const float*)d_in[1];
    const float* bx   = (const float*)d_in[2];
    const float* Wfx  = (const float*)d_in[3];
    const float* bfx  = (const float*)d_in[4];
    const float* Wsl  = (const float*)d_in[5];
    const float* bsl  = (const float*)d_in[6];
    const float* temp = (const float*)d_in[7];
    float* out = (float*)d_out;

    cudaFuncSetAttribute(k_fused, cudaFuncAttributeMaxDynamicSharedMemorySize, SMEM_BYTES);

    k_zero<<<256, 256>>>();
    dim3 grid(NCHUNK, H_, B_);
    k_fused<<<grid, 512, SMEM_BYTES>>>(x, Wx, bx, Wfx, bfx, Wsl, bsl, temp);
    k_final<<<256, 256>>>(out);
}

// round 11
// speedup vs baseline: 1.3942x; 1.3942x over previous
#include <cuda_runtime.h>
#include <cuda_fp16.h>
#include <cstdint>

#define B_ 2
#define N_ 65536
#define H_ 8
#define TILES_PER_CTA 8
#define NCHUNK 64

// ---- smem layout (byte offsets) ----
#define PWB   528                   // W pitch: 264 halves
#define PXB   144                   // x chunk pitch: 72 halves
#define PTB   272                   // transposed fx / w pitch: 136 halves
#define SW_B  0                     // W [n][k] fp16: n 0..63 = W_xs/T, 64..127 = W_fx  (67584)
#define SX_B  67584                 // x buf0 (18432) ; alias sFxT [d][tok] p272
#define SX1_B 86016                 // x buf1 (18432)
#define SP_B  104448                // w transposed [s][tok] p272 (17408)
#define SBS_B 121856                // fused logit bias /T (64 floats)
#define SBF_B 122112                // fx bias (64 floats)
#define SMEM_BYTES 122368

__device__ float  g_A[B_ * H_ * 64 * 64];
__device__ float  g_norm[B_ * H_ * 64];
__device__ __half g_Wxs[H_ * 64 * 256];   // [h][s][k], already /T
__device__ float  g_bS[H_ * 64];          // fused logit bias, already /T

__device__ __forceinline__ uint32_t smem_u32(const void* p) {
    uint32_t a;
    asm("{ .reg .u64 t; cvta.to.shared.u64 t, %1; cvt.u32.u64 %0, t; }" : "=r"(a) : "l"(p));
    return a;
}
__device__ __forceinline__ uint32_t f22h2(float a, float b) {
    __half2 h = __floats2half2_rn(a, b);
    return *reinterpret_cast<uint32_t*>(&h);
}
__device__ __forceinline__ void mma16(float* d, const unsigned* a, unsigned b0, unsigned b1) {
    asm volatile("mma.sync.aligned.m16n8k16.row.col.f32.f16.f16.f32 "
                 "{%0,%1,%2,%3},{%4,%5,%6,%7},{%8,%9},{%0,%1,%2,%3};"
                 : "+f"(d[0]), "+f"(d[1]), "+f"(d[2]), "+f"(d[3])
                 : "r"(a[0]), "r"(a[1]), "r"(a[2]), "r"(a[3]), "r"(b0), "r"(b1));
}
__device__ __forceinline__ void ldsm4(uint32_t addr, unsigned* r) {
    asm volatile("ldmatrix.sync.aligned.m8n8.x4.shared.b16 {%0,%1,%2,%3}, [%4];"
                 : "=r"(r[0]), "=r"(r[1]), "=r"(r[2]), "=r"(r[3]) : "r"(addr));
}

// ---- one-time: W_xs[h][s][k] = (W_x(head) @ Wsl)/T ; g_bS = (bx@Wsl + bsl)/T ----
__global__ __launch_bounds__(256, 4)
void k_prep(const float* __restrict__ Wx, const float* __restrict__ bx,
            const float* __restrict__ Wsl, const float* __restrict__ bsl,
            const float* __restrict__ temp)
{
    __shared__ float sWsl[4096];           // [d][s]
    const int h = blockIdx.x, tid = threadIdx.x;
    #pragma unroll
    for (int i = 0; i < 16; i++) sWsl[tid + i * 256] = Wsl[tid + i * 256];
    __syncthreads();

    float tv = fminf(fmaxf(temp[h], 0.5f), 5.0f);
    const float invT = 1.0f / tv;

    const int k  = blockIdx.y * 64 + (tid >> 2);
    const int sh = (tid & 3) * 16;
    const float4* wr = (const float4*)(Wx + (size_t)k * 512 + h * 64);
    float wv[64];
    #pragma unroll
    for (int i = 0; i < 16; i++) {
        float4 v = wr[i];
        wv[4 * i + 0] = v.x; wv[4 * i + 1] = v.y; wv[4 * i + 2] = v.z; wv[4 * i + 3] = v.w;
    }
    float a[16];
    #pragma unroll
    for (int j = 0; j < 16; j++) a[j] = 0.0f;
    #pragma unroll 8
    for (int d = 0; d < 64; d++) {
        float ws = wv[d];
        const float4* row = (const float4*)&sWsl[d * 64 + sh];
        #pragma unroll
        for (int j = 0; j < 4; j++) {
            float4 wl = row[j];
            a[4 * j + 0] += ws * wl.x; a[4 * j + 1] += ws * wl.y;
            a[4 * j + 2] += ws * wl.z; a[4 * j + 3] += ws * wl.w;
        }
    }
    #pragma unroll
    for (int j = 0; j < 16; j++)
        g_Wxs[h * 16384 + (sh + j) * 256 + k] = __float2half_rn(a[j] * invT);

    if (blockIdx.y == 0 && tid < 64) {
        float bbv = bsl[tid];
        #pragma unroll 8
        for (int d = 0; d < 64; d++) bbv += bx[h * 64 + d] * sWsl[d * 64 + tid];
        g_bS[h * 64 + tid] = bbv * invT;
    }
}

__global__ void k_zero() {
    int i = blockIdx.x * 256 + threadIdx.x;
    if (i < B_ * H_ * 64 * 64) g_A[i] = 0.0f;
    if (i < B_ * H_ * 64)      g_norm[i] = 0.0f;
}

__global__ __launch_bounds__(512, 1)
void k_fused(const float* __restrict__ x,
             const float* __restrict__ Wfx, const float* __restrict__ bfx)
{
    extern __shared__ char smb[];
    __half* sWh    = (__half*)(smb + SW_B);
    float*  sBiasS = (float*)(smb + SBS_B);
    float*  sBiasF = (float*)(smb + SBF_B);

    const uint32_t sb   = smem_u32(smb);
    const uint32_t sX0u = sb + SX_B;
    const uint32_t sX1u = sb + SX1_B;
    const uint32_t sWu  = sb + SW_B;
    const uint32_t sPu  = sb + SP_B;

    const int tid  = threadIdx.x;
    const int b    = blockIdx.z, h = blockIdx.y;
    const int lane = tid & 31, wid = tid >> 5;
    const int g    = lane >> 2, t = lane & 3;

    // main GEMM roles: 8 m-warps x 2 n-warps (nw0 = logits cols 0-63, nw1 = fx cols 64-127)
    const int mw = wid >> 1, nw = wid & 1;
    const int tokB = mw * 16;
    const int colBase = nw * 64;
    // agg roles: 4 (s) x 4 (d)
    const int sB3 = (wid >> 2) * 16, dB3 = (wid & 3) * 16;

    // ---- stage W: cols 0-63 from g_Wxs (vectorized), 64-127 from W_fx ----
    {
        const uint4* wxsrc = (const uint4*)(g_Wxs + h * 16384);
        #pragma unroll
        for (int it = 0; it < 4; it++) {
            int f = tid + it * 512;            // 0..2047 ; s = f>>5, q = f&31
            int s = f >> 5, q = f & 31;
            *(uint4*)(smb + SW_B + s * PWB + q * 16) = wxsrc[f];
        }
        const float4* Wfx4 = (const float4*)Wfx;
        #pragma unroll
        for (int it = 0; it < 8; it++) {
            int f = tid + it * 512;            // 0..4095
            int k = f >> 4, q = f & 15;
            float4 v = Wfx4[k * 128 + h * 16 + q];
            int n = 64 + 4 * q;
            sWh[(n + 0) * 264 + k] = __float2half_rn(v.x);
            sWh[(n + 1) * 264 + k] = __float2half_rn(v.y);
            sWh[(n + 2) * 264 + k] = __float2half_rn(v.z);
            sWh[(n + 3) * 264 + k] = __float2half_rn(v.w);
        }
        if (tid < 64)       sBiasS[tid] = g_bS[h * 64 + tid];
        else if (tid < 128) sBiasF[tid - 64] = bfx[h * 64 + (tid - 64)];
    }
    __syncthreads();

    // per-thread bias fragments: col = 8*(i>>1) + 2t + (i&1)
    float bR[16];
    {
        const float* btab = nw ? sBiasF : sBiasS;
        #pragma unroll
        for (int i = 0; i < 16; i++) bR[i] = btab[8 * (i >> 1) + 2 * t + (i & 1)];
    }

    // ldmatrix bases
    const int lr = lane & 15, lc = lane >> 4;
    const uint32_t aRel = (uint32_t)(tokB + lr) * PXB + lc * 16;
    const uint32_t bB0  = sWu + (uint32_t)(colBase + lr) * PWB + lc * 16;
    const uint32_t wA0  = sPu + (uint32_t)(sB3 + lr) * PTB + lc * 16;
    const uint32_t fB0  = sX0u + (uint32_t)(dB3 + lr) * PTB + lc * 16;

    float aggAcc[2][4];
    #pragma unroll
    for (int j = 0; j < 2; j++)
        #pragma unroll
        for (int e = 0; e < 4; e++) aggAcc[j][e] = 0.0f;
    float na[16];
    #pragma unroll
    for (int i = 0; i < 16; i++) na[i] = 0.0f;

    const float4* xg4 = (const float4*)x + (size_t)b * (size_t)N_ * 64;
    const int cTok = tid >> 2, cQ = tid & 3;
    const uint32_t stsRel = (uint32_t)cTok * PXB + cQ * 32;

    float4 xr[4];
    {
        const float4* src = xg4 + (size_t)((blockIdx.x * TILES_PER_CTA) * 128 + cTok) * 64 + cQ * 4;
        #pragma unroll
        for (int i = 0; i < 4; i++) xr[i] = src[i];
    }

    for (int tnum = 0; tnum < TILES_PER_CTA; tnum++) {
        const int n0 = (blockIdx.x * TILES_PER_CTA + tnum) * 128;
        const float4* srcRow = xg4 + (size_t)(n0 + cTok) * 64 + cQ * 4;
        __syncthreads();   // prev tile's agg / aliased-region reads done

        // stage chunk 0 -> buf0 ; prefetch chunk 1
        {
            uint4 u0, u1;
            u0.x = f22h2(xr[0].x, xr[0].y); u0.y = f22h2(xr[0].z, xr[0].w);
            u0.z = f22h2(xr[1].x, xr[1].y); u0.w = f22h2(xr[1].z, xr[1].w);
            u1.x = f22h2(xr[2].x, xr[2].y); u1.y = f22h2(xr[2].z, xr[2].w);
            u1.z = f22h2(xr[3].x, xr[3].y); u1.w = f22h2(xr[3].z, xr[3].w);
            *(uint4*)(smb + SX_B + stsRel)      = u0;
            *(uint4*)(smb + SX_B + stsRel + 16) = u1;
            const float4* src = srcRow + 16;
            #pragma unroll
            for (int i = 0; i < 4; i++) xr[i] = src[i];
        }
        __syncthreads();

        float acc[8][4];
        #pragma unroll
        for (int j = 0; j < 8; j++)
            #pragma unroll
            for (int e = 0; e < 4; e++) acc[j][e] = 0.0f;

        #pragma unroll
        for (int c = 0; c < 4; c++) {
            const uint32_t aB = ((c & 1) ? sX1u : sX0u) + aRel;
            const uint32_t kB = bB0 + (uint32_t)c * 128;
            #pragma unroll
            for (int ks = 0; ks < 4; ks++) {
                unsigned a[4], p[4];
                ldsm4(aB + ks * 32, a);
                #pragma unroll
                for (int q = 0; q < 4; q++) {
                    ldsm4(kB + q * (16 * PWB) + ks * 32, p);
                    mma16(acc[2 * q],     a, p[0], p[2]);
                    mma16(acc[2 * q + 1], a, p[1], p[3]);
                }
            }
            if (c < 3) {
                // stage chunk c+1 -> buf (c+1)&1 ; prefetch chunk c+2 (or next tile c0)
                uint4 u0, u1;
                u0.x = f22h2(xr[0].x, xr[0].y); u0.y = f22h2(xr[0].z, xr[0].w);
                u0.z = f22h2(xr[1].x, xr[1].y); u0.w = f22h2(xr[1].z, xr[1].w);
                u1.x = f22h2(xr[2].x, xr[2].y); u1.y = f22h2(xr[2].z, xr[2].w);
                u1.z = f22h2(xr[3].x, xr[3].y); u1.w = f22h2(xr[3].z, xr[3].w);
                char* dst = smb + ((c & 1) ? SX_B : SX1_B) + stsRel;
                *(uint4*)dst        = u0;
                *(uint4*)(dst + 16) = u1;
                if (c < 2) {
                    const float4* src = srcRow + (c + 2) * 16;
                    #pragma unroll
                    for (int i = 0; i < 4; i++) xr[i] = src[i];
                } else if (tnum + 1 < TILES_PER_CTA) {
                    const float4* src = xg4 + (size_t)(n0 + 128 + cTok) * 64 + cQ * 4;
                    #pragma unroll
                    for (int i = 0; i < 4; i++) xr[i] = src[i];
                }
                __syncthreads();
            }
        }

        // ---- epilogue (no sync needed first: fx->buf0 is disjoint from others' buf1 reads) ----
        const int r0 = tokB + g, r1 = r0 + 8;
        if (nw == 0) {
            float ex0[16], ex1[16];
            #pragma unroll
            for (int j = 0; j < 8; j++)
                #pragma unroll
                for (int e = 0; e < 2; e++) {
                    int i = 2 * j + e;
                    ex0[i] = __expf(acc[j][e]     + bR[i]);
                    ex1[i] = __expf(acc[j][2 + e] + bR[i]);
                }
            float s0 = 0.0f, s1 = 0.0f;
            #pragma unroll
            for (int i = 0; i < 16; i++) { s0 += ex0[i]; s1 += ex1[i]; }
            s0 += __shfl_xor_sync(0xffffffffu, s0, 1);
            s0 += __shfl_xor_sync(0xffffffffu, s0, 2);
            s1 += __shfl_xor_sync(0xffffffffu, s1, 1);
            s1 += __shfl_xor_sync(0xffffffffu, s1, 2);
            float inv0 = __frcp_rn(s0), inv1 = __frcp_rn(s1);
            #pragma unroll
            for (int i = 0; i < 16; i++) {
                int s = 8 * (i >> 1) + 2 * t + (i & 1);
                __half h0 = __float2half_rn(ex0[i] * inv0);
                __half h1 = __float2half_rn(ex1[i] * inv1);
                *(__half*)(smb + SP_B + s * PTB + r0 * 2) = h0;
                *(__half*)(smb + SP_B + s * PTB + r1 * 2) = h1;
                na[i] += __half2float(h0) + __half2float(h1);
            }
        } else {
            #pragma unroll
            for (int j = 0; j < 8; j++)
                #pragma unroll
                for (int e = 0; e < 2; e++) {
                    int i = 2 * j + e;
                    int d = 8 * j + 2 * t + e;
                    *(__half*)(smb + SX_B + d * PTB + r0 * 2) =
                        __float2half_rn(acc[j][e] + bR[i]);
                    *(__half*)(smb + SX_B + d * PTB + r1 * 2) =
                        __float2half_rn(acc[j][2 + e] + bR[i]);
                }
        }
        __syncthreads();

        // ---- aggregation: A[s,d] += w^T @ fx, K = 128 tokens ----
        #pragma unroll
        for (int ks = 0; ks < 8; ks++) {
            unsigned a[4], bb[4];
            ldsm4(wA0 + ks * 32, a);
            ldsm4(fB0 + ks * 32, bb);
            mma16(aggAcc[0], a, bb[0], bb[2]);
            mma16(aggAcc[1], a, bb[1], bb[3]);
        }
    }

    // ---- flush ----
    float* gA = g_A + (size_t)((b * H_ + h) * 64) * 64;
    #pragma unroll
    for (int j = 0; j < 2; j++) {
        int d0 = dB3 + 8 * j + 2 * t;
        atomicAdd(&gA[(sB3 + g) * 64 + d0],         aggAcc[j][0]);
        atomicAdd(&gA[(sB3 + g) * 64 + d0 + 1],     aggAcc[j][1]);
        atomicAdd(&gA[(sB3 + g + 8) * 64 + d0],     aggAcc[j][2]);
        atomicAdd(&gA[(sB3 + g + 8) * 64 + d0 + 1], aggAcc[j][3]);
    }
    if (nw == 0) {
        #pragma unroll
        for (int i = 0; i < 16; i++) {
            float v = na[i];
            v += __shfl_xor_sync(0xffffffffu, v, 4);
            v += __shfl_xor_sync(0xffffffffu, v, 8);
            v += __shfl_xor_sync(0xffffffffu, v, 16);
            if (lane < 4)
                atomicAdd(&g_norm[(b * H_ + h) * 64 + 8 * (i >> 1) + 2 * t + (i & 1)], v);
        }
    }
}

__global__ void k_final(float* __restrict__ out) {
    int i = blockIdx.x * 256 + threadIdx.x;
    out[i] = g_A[i] / (g_norm[i >> 6] + 0.01f);
}

extern "C" void kernel_launch(void* const* d_in, const int* in_sizes, int n_in,
                              void* d_out, int out_size) {
    const float* x    = (const float*)d_in[0];
    const float* Wx   = (const float*)d_in[1];
    const float* bx   = (const float*)d_in[2];
    const float* Wfx  = (const float*)d_in[3];
    const float* bfx  = (const float*)d_in[4];
    const float* Wsl  = (const float*)d_in[5];
    const float* bsl  = (const float*)d_in[6];
    const float* temp = (const float*)d_in[7];
    float* out = (float*)d_out;

    cudaFuncSetAttribute(k_fused, cudaFuncAttributeMaxDynamicSharedMemorySize, SMEM_BYTES);

    k_prep<<<dim3(H_, 4), 256>>>(Wx, bx, Wsl, bsl, temp);
    k_zero<<<256, 256>>>();
    dim3 grid(NCHUNK, H_, B_);
    k_fused<<<grid, 512, SMEM_BYTES>>>(x, Wfx, bfx);
    k_final<<<256, 256>>>(out);
}

// round 13
// speedup vs baseline: 1.4023x; 1.0058x over previous
#include <cuda_runtime.h>
#include <cuda_fp16.h>
#include <cstdint>

#define B_ 2
#define N_ 65536
#define H_ 8
#define TILES_PER_CTA 8
#define NCHUNK 128                  // CTAs per (b,h): 128 * 8 tiles * 64 tok = 65536

// ---- smem layout (byte offsets) ----
#define PWB   528                   // W pitch: 264 halves
#define PXB   144                   // x chunk pitch: 72 halves
#define PTB   144                   // transposed fx / w pitch: 72 halves (64 tok + pad)
#define SW_B  0                     // W [n][k] fp16: n 0..63 = W_xs/T, 64..127 = W_fx (67584)
#define SX_B  67584                 // x buf0 (9216) ; alias sFxT [d][tok] p144
#define SX1_B 76800                 // x buf1 (9216) ; alias sWgtT [s][tok] p144
#define SBS_B 86016                 // fused logit bias /T (64 floats)
#define SBF_B 86272                 // fx bias (64 floats)
#define SMEM_BYTES 86528

__device__ float  g_A[B_ * H_ * 64 * 64];
__device__ float  g_norm[B_ * H_ * 64];
__device__ __half g_Wxs[H_ * 64 * 256];   // [h][s][k], already /T
__device__ float  g_bS[H_ * 64];          // fused logit bias, already /T

__device__ __forceinline__ uint32_t smem_u32(const void* p) {
    uint32_t a;
    asm("{ .reg .u64 t; cvta.to.shared.u64 t, %1; cvt.u32.u64 %0, t; }" : "=r"(a) : "l"(p));
    return a;
}
__device__ __forceinline__ uint32_t f22h2(float a, float b) {
    __half2 h = __floats2half2_rn(a, b);
    return *reinterpret_cast<uint32_t*>(&h);
}
__device__ __forceinline__ void mma16(float* d, const unsigned* a, unsigned b0, unsigned b1) {
    asm volatile("mma.sync.aligned.m16n8k16.row.col.f32.f16.f16.f32 "
                 "{%0,%1,%2,%3},{%4,%5,%6,%7},{%8,%9},{%0,%1,%2,%3};"
                 : "+f"(d[0]), "+f"(d[1]), "+f"(d[2]), "+f"(d[3])
                 : "r"(a[0]), "r"(a[1]), "r"(a[2]), "r"(a[3]), "r"(b0), "r"(b1));
}
__device__ __forceinline__ void ldsm4(uint32_t addr, unsigned* r) {
    asm volatile("ldmatrix.sync.aligned.m8n8.x4.shared.b16 {%0,%1,%2,%3}, [%4];"
                 : "=r"(r[0]), "=r"(r[1]), "=r"(r[2]), "=r"(r[3]) : "r"(addr));
}

// ---- one-time: W_xs[h][s][k] = (W_x(head) @ Wsl)/T ; g_bS = (bx@Wsl + bsl)/T ----
__global__ __launch_bounds__(256, 4)
void k_prep(const float* __restrict__ Wx, const float* __restrict__ bx,
            const float* __restrict__ Wsl, const float* __restrict__ bsl,
            const float* __restrict__ temp)
{
    __shared__ float sWsl[4096];           // [d][s]
    const int h = blockIdx.x, tid = threadIdx.x;
    #pragma unroll
    for (int i = 0; i < 16; i++) sWsl[tid + i * 256] = Wsl[tid + i * 256];
    __syncthreads();

    float tv = fminf(fmaxf(temp[h], 0.5f), 5.0f);
    const float invT = 1.0f / tv;

    const int k  = blockIdx.y * 64 + (tid >> 2);
    const int sh = (tid & 3) * 16;
    const float4* wr = (const float4*)(Wx + (size_t)k * 512 + h * 64);
    float wv[64];
    #pragma unroll
    for (int i = 0; i < 16; i++) {
        float4 v = wr[i];
        wv[4 * i + 0] = v.x; wv[4 * i + 1] = v.y; wv[4 * i + 2] = v.z; wv[4 * i + 3] = v.w;
    }
    float a[16];
    #pragma unroll
    for (int j = 0; j < 16; j++) a[j] = 0.0f;
    #pragma unroll 8
    for (int d = 0; d < 64; d++) {
        float ws = wv[d];
        const float4* row = (const float4*)&sWsl[d * 64 + sh];
        #pragma unroll
        for (int j = 0; j < 4; j++) {
            float4 wl = row[j];
            a[4 * j + 0] += ws * wl.x; a[4 * j + 1] += ws * wl.y;
            a[4 * j + 2] += ws * wl.z; a[4 * j + 3] += ws * wl.w;
        }
    }
    #pragma unroll
    for (int j = 0; j < 16; j++)
        g_Wxs[h * 16384 + (sh + j) * 256 + k] = __float2half_rn(a[j] * invT);

    if (blockIdx.y == 0 && tid < 64) {
        float bbv = bsl[tid];
        #pragma unroll 8
        for (int d = 0; d < 64; d++) bbv += bx[h * 64 + d] * sWsl[d * 64 + tid];
        g_bS[h * 64 + tid] = bbv * invT;
    }
}

__global__ void k_zero() {
    int i = blockIdx.x * 256 + threadIdx.x;
    if (i < B_ * H_ * 64 * 64) g_A[i] = 0.0f;
    if (i < B_ * H_ * 64)      g_norm[i] = 0.0f;
}

__global__ __launch_bounds__(256, 2)
void k_fused(const float* __restrict__ x,
             const float* __restrict__ Wfx, const float* __restrict__ bfx)
{
    extern __shared__ char smb[];
    __half* sWh    = (__half*)(smb + SW_B);
    float*  sBiasS = (float*)(smb + SBS_B);
    float*  sBiasF = (float*)(smb + SBF_B);

    const uint32_t sb   = smem_u32(smb);
    const uint32_t sX0u = sb + SX_B;
    const uint32_t sX1u = sb + SX1_B;
    const uint32_t sWu  = sb + SW_B;

    const int tid  = threadIdx.x;
    const int b    = blockIdx.z, h = blockIdx.y;
    const int lane = tid & 31, wid = tid >> 5;
    const int g    = lane >> 2, t = lane & 3;

    // main GEMM roles: 4 m-warps x 2 n-warps (nw0 = logit cols 0-63, nw1 = fx cols 64-127)
    const int mw = wid >> 1, nw = wid & 1;
    const int tokB = mw * 16;
    const int colBase = nw * 64;
    // agg roles: 4 (s) x 2 (d)
    const int sB3 = (wid >> 1) * 16, dB3 = (wid & 1) * 32;

    // ---- stage W: cols 0-63 from g_Wxs (vectorized), 64-127 from W_fx ----
    {
        const uint4* wxsrc = (const uint4*)(g_Wxs + h * 16384);
        #pragma unroll
        for (int it = 0; it < 8; it++) {
            int f = tid + it * 256;            // 0..2047 ; s = f>>5, q = f&31
            int s = f >> 5, q = f & 31;
            *(uint4*)(smb + SW_B + s * PWB + q * 16) = wxsrc[f];
        }
        const float4* Wfx4 = (const float4*)Wfx;
        #pragma unroll
        for (int it = 0; it < 16; it++) {
            int f = tid + it * 256;            // 0..4095
            int k = f >> 4, q = f & 15;
            float4 v = Wfx4[k * 128 + h * 16 + q];
            int n = 64 + 4 * q;
            sWh[(n + 0) * 264 + k] = __float2half_rn(v.x);
            sWh[(n + 1) * 264 + k] = __float2half_rn(v.y);
            sWh[(n + 2) * 264 + k] = __float2half_rn(v.z);
            sWh[(n + 3) * 264 + k] = __float2half_rn(v.w);
        }
        if (tid < 64)       sBiasS[tid] = g_bS[h * 64 + tid];
        else if (tid < 128) sBiasF[tid - 64] = bfx[h * 64 + (tid - 64)];
    }
    __syncthreads();

    // ldmatrix bases
    const int lr = lane & 15, lc = lane >> 4;
    const uint32_t aRel = (uint32_t)(tokB + lr) * PXB + lc * 16;
    const uint32_t bB0  = sWu + (uint32_t)(colBase + lr) * PWB + lc * 16;
    const uint32_t wA0  = sX1u + (uint32_t)(sB3 + lr) * PTB + lc * 16;
    const uint32_t fB0  = sX0u + (uint32_t)(dB3 + lr) * PTB + lc * 16;

    float aggAcc[4][4];
    #pragma unroll
    for (int j = 0; j < 4; j++)
        #pragma unroll
        for (int e = 0; e < 4; e++) aggAcc[j][e] = 0.0f;
    float na[16];
    #pragma unroll
    for (int i = 0; i < 16; i++) na[i] = 0.0f;

    const float4* xg4 = (const float4*)x + (size_t)b * (size_t)N_ * 64;
    const int cTok = tid >> 2, cQ = tid & 3;
    const uint32_t stsRel = (uint32_t)cTok * PXB + cQ * 32;

    float4 xr[4];
    {
        const float4* src = xg4 + (size_t)((blockIdx.x * TILES_PER_CTA) * 64 + cTok) * 64 + cQ * 4;
        #pragma unroll
        for (int i = 0; i < 4; i++) xr[i] = src[i];
    }

    for (int tnum = 0; tnum < TILES_PER_CTA; tnum++) {
        const int n0 = (blockIdx.x * TILES_PER_CTA + tnum) * 64;
        const float4* srcRow = xg4 + (size_t)(n0 + cTok) * 64 + cQ * 4;
        __syncthreads();   // prev tile's agg reads of buf0/buf1 done

        // stage chunk 0 -> buf0 ; prefetch chunk 1
        {
            uint4 u0, u1;
            u0.x = f22h2(xr[0].x, xr[0].y); u0.y = f22h2(xr[0].z, xr[0].w);
            u0.z = f22h2(xr[1].x, xr[1].y); u0.w = f22h2(xr[1].z, xr[1].w);
            u1.x = f22h2(xr[2].x, xr[2].y); u1.y = f22h2(xr[2].z, xr[2].w);
            u1.z = f22h2(xr[3].x, xr[3].y); u1.w = f22h2(xr[3].z, xr[3].w);
            *(uint4*)(smb + SX_B + stsRel)      = u0;
            *(uint4*)(smb + SX_B + stsRel + 16) = u1;
            const float4* src = srcRow + 16;
            #pragma unroll
            for (int i = 0; i < 4; i++) xr[i] = src[i];
        }
        __syncthreads();

        float acc[8][4];
        #pragma unroll
        for (int j = 0; j < 8; j++)
            #pragma unroll
            for (int e = 0; e < 4; e++) acc[j][e] = 0.0f;

        #pragma unroll
        for (int c = 0; c < 4; c++) {
            const uint32_t aB = ((c & 1) ? sX1u : sX0u) + aRel;
            const uint32_t kB = bB0 + (uint32_t)c * 128;
            #pragma unroll
            for (int ks = 0; ks < 4; ks++) {
                unsigned a[4], p[4];
                ldsm4(aB + ks * 32, a);
                #pragma unroll
                for (int q = 0; q < 4; q++) {
                    ldsm4(kB + q * (16 * PWB) + ks * 32, p);
                    mma16(acc[2 * q],     a, p[0], p[2]);
                    mma16(acc[2 * q + 1], a, p[1], p[3]);
                }
            }
            if (c < 3) {
                uint4 u0, u1;
                u0.x = f22h2(xr[0].x, xr[0].y); u0.y = f22h2(xr[0].z, xr[0].w);
                u0.z = f22h2(xr[1].x, xr[1].y); u0.w = f22h2(xr[1].z, xr[1].w);
                u1.x = f22h2(xr[2].x, xr[2].y); u1.y = f22h2(xr[2].z, xr[2].w);
                u1.z = f22h2(xr[3].x, xr[3].y); u1.w = f22h2(xr[3].z, xr[3].w);
                char* dst = smb + ((c & 1) ? SX_B : SX1_B) + stsRel;
                *(uint4*)dst        = u0;
                *(uint4*)(dst + 16) = u1;
                if (c < 2) {
                    const float4* src = srcRow + (c + 2) * 16;
                    #pragma unroll
                    for (int i = 0; i < 4; i++) xr[i] = src[i];
                } else if (tnum + 1 < TILES_PER_CTA) {
                    const float4* src = xg4 + (size_t)(n0 + 64 + cTok) * 64 + cQ * 4;
                    #pragma unroll
                    for (int i = 0; i < 4; i++) xr[i] = src[i];
                }
                __syncthreads();
            }
        }
        __syncthreads();   // last-chunk reads of buf1 done before wT overwrites it

        // ---- epilogue: nw0 in-warp softmax (exp in place); nw1 fx stores ----
        const int r0 = tokB + g, r1 = r0 + 8;
        if (nw == 0) {
            float s0 = 0.0f, s1 = 0.0f;
            #pragma unroll
            for (int j = 0; j < 8; j++)
                #pragma unroll
                for (int e = 0; e < 2; e++) {
                    float bb = sBiasS[8 * j + 2 * t + e];
                    acc[j][e]     = __expf(acc[j][e]     + bb); s0 += acc[j][e];
                    acc[j][2 + e] = __expf(acc[j][2 + e] + bb); s1 += acc[j][2 + e];
                }
            s0 += __shfl_xor_sync(0xffffffffu, s0, 1);
            s0 += __shfl_xor_sync(0xffffffffu, s0, 2);
            s1 += __shfl_xor_sync(0xffffffffu, s1, 1);
            s1 += __shfl_xor_sync(0xffffffffu, s1, 2);
            float inv0 = __frcp_rn(s0), inv1 = __frcp_rn(s1);
            #pragma unroll
            for (int j = 0; j < 8; j++)
                #pragma unroll
                for (int e = 0; e < 2; e++) {
                    int s = 8 * j + 2 * t + e;
                    __half h0 = __float2half_rn(acc[j][e]     * inv0);
                    __half h1 = __float2half_rn(acc[j][2 + e] * inv1);
                    *(__half*)(smb + SX1_B + s * PTB + r0 * 2) = h0;
                    *(__half*)(smb + SX1_B + s * PTB + r1 * 2) = h1;
                    na[2 * j + e] += __half2float(h0) + __half2float(h1);
                }
        } else {
            #pragma unroll
            for (int j = 0; j < 8; j++)
                #pragma unroll
                for (int e = 0; e < 2; e++) {
                    int d = 8 * j + 2 * t + e;
                    float bb = sBiasF[d];
                    *(__half*)(smb + SX_B + d * PTB + r0 * 2) =
                        __float2half_rn(acc[j][e] + bb);
                    *(__half*)(smb + SX_B + d * PTB + r1 * 2) =
                        __float2half_rn(acc[j][2 + e] + bb);
                }
        }
        __syncthreads();

        // ---- aggregation: A[s,d] += w^T @ fx, K = 64 tokens ----
        #pragma unroll
        for (int ks = 0; ks < 4; ks++) {
            unsigned a[4], bb[4];
            ldsm4(wA0 + ks * 32, a);
            ldsm4(fB0 + ks * 32, bb);
            mma16(aggAcc[0], a, bb[0], bb[2]);
            mma16(aggAcc[1], a, bb[1], bb[3]);
            ldsm4(fB0 + 16 * PTB + ks * 32, bb);
            mma16(aggAcc[2], a, bb[0], bb[2]);
            mma16(aggAcc[3], a, bb[1], bb[3]);
        }
    }

    // ---- flush ----
    float* gA = g_A + (size_t)((b * H_ + h) * 64) * 64;
    #pragma unroll
    for (int j = 0; j < 4; j++) {
        int d0 = dB3 + 8 * j + 2 * t;
        atomicAdd(&gA[(sB3 + g) * 64 + d0],         aggAcc[j][0]);
        atomicAdd(&gA[(sB3 + g) * 64 + d0 + 1],     aggAcc[j][1]);
        atomicAdd(&gA[(sB3 + g + 8) * 64 + d0],     aggAcc[j][2]);
        atomicAdd(&gA[(sB3 + g + 8) * 64 + d0 + 1], aggAcc[j][3]);
    }
    if (nw == 0) {
        #pragma unroll
        for (int i = 0; i < 16; i++) {
            float v = na[i];
            v += __shfl_xor_sync(0xffffffffu, v, 4);
            v += __shfl_xor_sync(0xffffffffu, v, 8);
            v += __shfl_xor_sync(0xffffffffu, v, 16);
            if (lane < 4)
                atomicAdd(&g_norm[(b * H_ + h) * 64 + 8 * (i >> 1) + 2 * t + (i & 1)], v);
        }
    }
}

__global__ void k_final(float* __restrict__ out) {
    int i = blockIdx.x * 256 + threadIdx.x;
    out[i] = g_A[i] / (g_norm[i >> 6] + 0.01f);
}

extern "C" void kernel_launch(void* const* d_in, const int* in_sizes, int n_in,
                              void* d_out, int out_size) {
    const float* x    = (const float*)d_in[0];
    const float* Wx   = (const float*)d_in[1];
    const float* bx   = (const float*)d_in[2];
    const float* Wfx  = (const float*)d_in[3];
    const float* bfx  = (const float*)d_in[4];
    const float* Wsl  = (const float*)d_in[5];
    const float* bsl  = (const float*)d_in[6];
    const float* temp = (const float*)d_in[7];
    float* out = (float*)d_out;

    cudaFuncSetAttribute(k_fused, cudaFuncAttributeMaxDynamicSharedMemorySize, SMEM_BYTES);

    k_prep<<<dim3(H_, 4), 256>>>(Wx, bx, Wsl, bsl, temp);
    k_zero<<<256, 256>>>();
    dim3 grid(NCHUNK, H_, B_);
    k_fused<<<grid, 256, SMEM_BYTES>>>(x, Wfx, bfx);
    k_final<<<256, 256>>>(out);
}

// round 15
// speedup vs baseline: 1.5147x; 1.0801x over previous
#include <cuda_runtime.h>
#include <cuda_fp16.h>
#include <cstdint>

#define B_ 2
#define N_ 65536
#define H_ 8
#define TILES_PER_CTA 8
#define NCHUNK 64                   // CTAs per (b,h): 64 * 8 tiles * 128 tok = 65536

// ---- smem layout (byte offsets) ----
#define PWB   528                   // W pitch: 264 halves
#define PXB   80                    // x chunk pitch: 40 halves (32 k + pad) ; 5 x 16B units, gcd(5,8)=1
#define PTB   272                   // transposed fx / w pitch: 136 halves (128 tok + pad)
#define SW_B  0                     // W [n][k] fp16: n 0..63 = W_xs/T, 64..127 = W_fx (67584)
#define SXB0  67584                 // x buf0 (10240) ┐ fxT [d][tok] p272 (17408) aliases buf0+buf1
#define SXB1  77824                 // x buf1 (10240) ┘
#define SWT_B 88064                 // wT [s][tok] p272 (17408) — own region
#define SBS_B 105472                // fused logit bias /T (64 floats)
#define SBF_B 105728                // fx bias (64 floats)
#define SMEM_BYTES 105984

__device__ float  g_A[B_ * H_ * 64 * 64];
__device__ float  g_norm[B_ * H_ * 64];
__device__ __half g_Wxs[H_ * 64 * 256];   // [h][s][k], already /T
__device__ float  g_bS[H_ * 64];          // fused logit bias, already /T

__device__ __forceinline__ uint32_t smem_u32(const void* p) {
    uint32_t a;
    asm("{ .reg .u64 t; cvta.to.shared.u64 t, %1; cvt.u32.u64 %0, t; }" : "=r"(a) : "l"(p));
    return a;
}
__device__ __forceinline__ uint32_t f22h2(float a, float b) {
    __half2 h = __floats2half2_rn(a, b);
    return *reinterpret_cast<uint32_t*>(&h);
}
__device__ __forceinline__ void mma16(float* d, const unsigned* a, unsigned b0, unsigned b1) {
    asm volatile("mma.sync.aligned.m16n8k16.row.col.f32.f16.f16.f32 "
                 "{%0,%1,%2,%3},{%4,%5,%6,%7},{%8,%9},{%0,%1,%2,%3};"
                 : "+f"(d[0]), "+f"(d[1]), "+f"(d[2]), "+f"(d[3])
                 : "r"(a[0]), "r"(a[1]), "r"(a[2]), "r"(a[3]), "r"(b0), "r"(b1));
}
__device__ __forceinline__ void ldsm4(uint32_t addr, unsigned* r) {
    asm volatile("ldmatrix.sync.aligned.m8n8.x4.shared.b16 {%0,%1,%2,%3}, [%4];"
                 : "=r"(r[0]), "=r"(r[1]), "=r"(r[2]), "=r"(r[3]) : "r"(addr));
}
__device__ __forceinline__ float h2sum(unsigned u) {
    float2 v = __half22float2(*reinterpret_cast<__half2*>(&u));
    return v.x + v.y;
}

// ---- one-time: W_xs[h][s][k] = (W_x(head) @ Wsl)/T ; g_bS = (bx@Wsl + bsl)/T ----
__global__ __launch_bounds__(256, 4)
void k_prep(const float* __restrict__ Wx, const float* __restrict__ bx,
            const float* __restrict__ Wsl, const float* __restrict__ bsl,
            const float* __restrict__ temp)
{
    __shared__ float sWsl[4096];           // [d][s]
    const int h = blockIdx.x, tid = threadIdx.x;
    #pragma unroll
    for (int i = 0; i < 16; i++) sWsl[tid + i * 256] = Wsl[tid + i * 256];
    __syncthreads();

    float tv = fminf(fmaxf(temp[h], 0.5f), 5.0f);
    const float invT = 1.0f / tv;

    const int k  = blockIdx.y * 64 + (tid >> 2);
    const int sh = (tid & 3) * 16;
    const float4* wr = (const float4*)(Wx + (size_t)k * 512 + h * 64);
    float wv[64];
    #pragma unroll
    for (int i = 0; i < 16; i++) {
        float4 v = wr[i];
        wv[4 * i + 0] = v.x; wv[4 * i + 1] = v.y; wv[4 * i + 2] = v.z; wv[4 * i + 3] = v.w;
    }
    float a[16];
    #pragma unroll
    for (int j = 0; j < 16; j++) a[j] = 0.0f;
    #pragma unroll 8
    for (int d = 0; d < 64; d++) {
        float ws = wv[d];
        const float4* row = (const float4*)&sWsl[d * 64 + sh];
        #pragma unroll
        for (int j = 0; j < 4; j++) {
            float4 wl = row[j];
            a[4 * j + 0] += ws * wl.x; a[4 * j + 1] += ws * wl.y;
            a[4 * j + 2] += ws * wl.z; a[4 * j + 3] += ws * wl.w;
        }
    }
    #pragma unroll
    for (int j = 0; j < 16; j++)
        g_Wxs[h * 16384 + (sh + j) * 256 + k] = __float2half_rn(a[j] * invT);

    if (blockIdx.y == 0 && tid < 64) {
        float bbv = bsl[tid];
        #pragma unroll 8
        for (int d = 0; d < 64; d++) bbv += bx[h * 64 + d] * sWsl[d * 64 + tid];
        g_bS[h * 64 + tid] = bbv * invT;
    }
}

__global__ void k_zero() {
    int i = blockIdx.x * 256 + threadIdx.x;
    if (i < B_ * H_ * 64 * 64) g_A[i] = 0.0f;
    if (i < B_ * H_ * 64)      g_norm[i] = 0.0f;
}

__global__ __launch_bounds__(256, 2)
void k_fused(const float* __restrict__ x,
             const float* __restrict__ Wfx, const float* __restrict__ bfx)
{
    extern __shared__ char smb[];
    __half* sWh    = (__half*)(smb + SW_B);
    float*  sBiasS = (float*)(smb + SBS_B);
    float*  sBiasF = (float*)(smb + SBF_B);

    const uint32_t sb   = smem_u32(smb);
    const uint32_t sX0u = sb + SXB0;
    const uint32_t sX1u = sb + SXB1;
    const uint32_t sWu  = sb + SW_B;

    const int tid  = threadIdx.x;
    const int b    = blockIdx.z, h = blockIdx.y;
    const int lane = tid & 31, wid = tid >> 5;
    const int g    = lane >> 2, t = lane & 3;

    // main GEMM roles: 4 m-warps (32 tok) x 2 n-warps
    const int mw = wid >> 1, nw = wid & 1;
    const int tokB = mw * 32;
    const int colBase = nw * 64;
    // agg roles: 4 (s) x 2 (d)
    const int sB3 = (wid >> 1) * 16, dB3 = (wid & 1) * 32;

    // ---- stage W: cols 0-63 from g_Wxs (vectorized), 64-127 from W_fx ----
    {
        const uint4* wxsrc = (const uint4*)(g_Wxs + h * 16384);
        #pragma unroll
        for (int it = 0; it < 8; it++) {
            int f = tid + it * 256;            // 0..2047
            int s = f >> 5, q = f & 31;
            *(uint4*)(smb + SW_B + s * PWB + q * 16) = wxsrc[f];
        }
        const float4* Wfx4 = (const float4*)Wfx;
        #pragma unroll
        for (int it = 0; it < 16; it++) {
            int f = tid + it * 256;            // 0..4095
            int k = f >> 4, q = f & 15;
            float4 v = Wfx4[k * 128 + h * 16 + q];
            int n = 64 + 4 * q;
            sWh[(n + 0) * 264 + k] = __float2half_rn(v.x);
            sWh[(n + 1) * 264 + k] = __float2half_rn(v.y);
            sWh[(n + 2) * 264 + k] = __float2half_rn(v.z);
            sWh[(n + 3) * 264 + k] = __float2half_rn(v.w);
        }
        if (tid < 64)       sBiasS[tid] = g_bS[h * 64 + tid];
        else if (tid < 128) sBiasF[tid - 64] = bfx[h * 64 + (tid - 64)];
    }
    __syncthreads();

    // ldmatrix bases
    const int lr = lane & 15, lc = lane >> 4;
    const uint32_t aRel = (uint32_t)(tokB + lr) * PXB + lc * 16;
    const uint32_t bB0  = sWu + (uint32_t)(colBase + lr) * PWB + lc * 16;
    const uint32_t wA0  = sb + SWT_B + (uint32_t)(sB3 + lr) * PTB + lc * 16;
    const uint32_t fB0  = sb + SXB0 + (uint32_t)(dB3 + lr) * PTB + lc * 16;

    float aggAcc[4][4];
    #pragma unroll
    for (int j = 0; j < 4; j++)
        #pragma unroll
        for (int e = 0; e < 4; e++) aggAcc[j][e] = 0.0f;
    float na0 = 0.0f, na1 = 0.0f;

    const float4* xg4 = (const float4*)x + (size_t)b * (size_t)N_ * 64;
    const int cTok = tid >> 1, cHalf = tid & 1;   // thread: 16 floats (half a 32-k row)
    const uint32_t stsRel = (uint32_t)cTok * PXB + cHalf * 32;

    float4 xr[4];
    {   // prefetch tile 0 chunk 0 (k 0..31)
        const float4* src = xg4 + (size_t)((blockIdx.x * TILES_PER_CTA) * 128 + cTok) * 64 + cHalf * 4;
        #pragma unroll
        for (int i = 0; i < 4; i++) xr[i] = src[i];
    }

    for (int tnum = 0; tnum < TILES_PER_CTA; tnum++) {
        const int n0 = (blockIdx.x * TILES_PER_CTA + tnum) * 128;
        const float4* srcRow = xg4 + (size_t)(n0 + cTok) * 64 + cHalf * 4;
        __syncthreads();   // prev tile's agg reads (fxT over bufs) done

        // stage chunk 0 -> buf0 ; prefetch chunk 1
        {
            uint4 u0, u1;
            u0.x = f22h2(xr[0].x, xr[0].y); u0.y = f22h2(xr[0].z, xr[0].w);
            u0.z = f22h2(xr[1].x, xr[1].y); u0.w = f22h2(xr[1].z, xr[1].w);
            u1.x = f22h2(xr[2].x, xr[2].y); u1.y = f22h2(xr[2].z, xr[2].w);
            u1.z = f22h2(xr[3].x, xr[3].y); u1.w = f22h2(xr[3].z, xr[3].w);
            *(uint4*)(smb + SXB0 + stsRel)      = u0;
            *(uint4*)(smb + SXB0 + stsRel + 16) = u1;
            const float4* src = srcRow + 8;
            #pragma unroll
            for (int i = 0; i < 4; i++) xr[i] = src[i];
        }
        __syncthreads();

        float acc[2][8][4];
        #pragma unroll
        for (int i = 0; i < 2; i++)
            #pragma unroll
            for (int j = 0; j < 8; j++)
                #pragma unroll
                for (int e = 0; e < 4; e++) acc[i][j][e] = 0.0f;

        #pragma unroll
        for (int c = 0; c < 8; c++) {
            const uint32_t aB = ((c & 1) ? sX1u : sX0u) + aRel;
            const uint32_t kB = bB0 + (uint32_t)c * 64;
            #pragma unroll
            for (int ks = 0; ks < 2; ks++) {
                unsigned a0[4], a1[4], p[4];
                ldsm4(aB + ks * 32, a0);
                ldsm4(aB + 16 * PXB + ks * 32, a1);
                #pragma unroll
                for (int q = 0; q < 4; q++) {
                    ldsm4(kB + q * (16 * PWB) + ks * 32, p);
                    mma16(acc[0][2 * q],     a0, p[0], p[2]);
                    mma16(acc[0][2 * q + 1], a0, p[1], p[3]);
                    mma16(acc[1][2 * q],     a1, p[0], p[2]);
                    mma16(acc[1][2 * q + 1], a1, p[1], p[3]);
                }
            }
            if (c < 7) {
                // stage chunk c+1 -> other buf ; prefetch chunk c+2 (or next tile c0)
                uint4 u0, u1;
                u0.x = f22h2(xr[0].x, xr[0].y); u0.y = f22h2(xr[0].z, xr[0].w);
                u0.z = f22h2(xr[1].x, xr[1].y); u0.w = f22h2(xr[1].z, xr[1].w);
                u1.x = f22h2(xr[2].x, xr[2].y); u1.y = f22h2(xr[2].z, xr[2].w);
                u1.z = f22h2(xr[3].x, xr[3].y); u1.w = f22h2(xr[3].z, xr[3].w);
                char* dst = smb + ((c & 1) ? SXB0 : SXB1) + stsRel;
                *(uint4*)dst        = u0;
                *(uint4*)(dst + 16) = u1;
                if (c < 6) {
                    const float4* src = srcRow + (c + 2) * 8;
                    #pragma unroll
                    for (int i = 0; i < 4; i++) xr[i] = src[i];
                } else if (tnum + 1 < TILES_PER_CTA) {
                    const float4* src = xg4 + (size_t)(n0 + 128 + cTok) * 64 + cHalf * 4;
                    #pragma unroll
                    for (int i = 0; i < 4; i++) xr[i] = src[i];
                }
                __syncthreads();
            }
        }
        __syncthreads();   // chunk-7 reads of buf1 done before fxT overwrites bufs

        // ---- epilogue: nw0 in-warp softmax (exp in place); nw1 fx stores ----
        if (nw == 0) {
            float s00 = 0.f, s01 = 0.f, s10 = 0.f, s11 = 0.f;
            #pragma unroll
            for (int j = 0; j < 8; j++)
                #pragma unroll
                for (int e = 0; e < 2; e++) {
                    float bb = sBiasS[8 * j + 2 * t + e];
                    acc[0][j][e]     = __expf(acc[0][j][e]     + bb); s00 += acc[0][j][e];
                    acc[0][j][2 + e] = __expf(acc[0][j][2 + e] + bb); s01 += acc[0][j][2 + e];
                    acc[1][j][e]     = __expf(acc[1][j][e]     + bb); s10 += acc[1][j][e];
                    acc[1][j][2 + e] = __expf(acc[1][j][2 + e] + bb); s11 += acc[1][j][2 + e];
                }
            s00 += __shfl_xor_sync(0xffffffffu, s00, 1); s00 += __shfl_xor_sync(0xffffffffu, s00, 2);
            s01 += __shfl_xor_sync(0xffffffffu, s01, 1); s01 += __shfl_xor_sync(0xffffffffu, s01, 2);
            s10 += __shfl_xor_sync(0xffffffffu, s10, 1); s10 += __shfl_xor_sync(0xffffffffu, s10, 2);
            s11 += __shfl_xor_sync(0xffffffffu, s11, 1); s11 += __shfl_xor_sync(0xffffffffu, s11, 2);
            float i00 = __frcp_rn(s00), i01 = __frcp_rn(s01);
            float i10 = __frcp_rn(s10), i11 = __frcp_rn(s11);
            #pragma unroll
            for (int i = 0; i < 2; i++) {
                const int r0 = tokB + 16 * i + g, r1 = r0 + 8;
                float iv0 = i ? i10 : i00, iv1 = i ? i11 : i01;
                #pragma unroll
                for (int j = 0; j < 8; j++)
                    #pragma unroll
                    for (int e = 0; e < 2; e++) {
                        int s = 8 * j + 2 * t + e;
                        *(__half*)(smb + SWT_B + s * PTB + r0 * 2) =
                            __float2half_rn(acc[i][j][e] * iv0);
                        *(__half*)(smb + SWT_B + s * PTB + r1 * 2) =
                            __float2half_rn(acc[i][j][2 + e] * iv1);
                    }
            }
        } else {
            #pragma unroll
            for (int i = 0; i < 2; i++) {
                const int r0 = tokB + 16 * i + g, r1 = r0 + 8;
                #pragma unroll
                for (int j = 0; j < 8; j++)
                    #pragma unroll
                    for (int e = 0; e < 2; e++) {
                        int d = 8 * j + 2 * t + e;
                        float bb = sBiasF[d];
                        *(__half*)(smb + SXB0 + d * PTB + r0 * 2) =
                            __float2half_rn(acc[i][j][e] + bb);
                        *(__half*)(smb + SXB0 + d * PTB + r1 * 2) =
                            __float2half_rn(acc[i][j][2 + e] + bb);
                    }
            }
        }
        __syncthreads();

        // ---- aggregation: A[s,d] += w^T @ fx, K = 128 tokens ----
        // norm accumulated from the wT fragments (dB3==0 warps only; rows g / g+8)
        #pragma unroll
        for (int ks = 0; ks < 8; ks++) {
            unsigned a[4], bb[4];
            ldsm4(wA0 + ks * 32, a);
            if (dB3 == 0) {
                na0 += h2sum(a[0]) + h2sum(a[2]);
                na1 += h2sum(a[1]) + h2sum(a[3]);
            }
            ldsm4(fB0 + ks * 32, bb);
            mma16(aggAcc[0], a, bb[0], bb[2]);
            mma16(aggAcc[1], a, bb[1], bb[3]);
            ldsm4(fB0 + 16 * PTB + ks * 32, bb);
            mma16(aggAcc[2], a, bb[0], bb[2]);
            mma16(aggAcc[3], a, bb[1], bb[3]);
        }
    }

    // ---- flush ----
    float* gA = g_A + (size_t)((b * H_ + h) * 64) * 64;
    #pragma unroll
    for (int j = 0; j < 4; j++) {
        int d0 = dB3 + 8 * j + 2 * t;
        atomicAdd(&gA[(sB3 + g) * 64 + d0],         aggAcc[j][0]);
        atomicAdd(&gA[(sB3 + g) * 64 + d0 + 1],     aggAcc[j][1]);
        atomicAdd(&gA[(sB3 + g + 8) * 64 + d0],     aggAcc[j][2]);
        atomicAdd(&gA[(sB3 + g + 8) * 64 + d0 + 1], aggAcc[j][3]);
    }
    if (dB3 == 0) {
        na0 += __shfl_xor_sync(0xffffffffu, na0, 1);
        na0 += __shfl_xor_sync(0xffffffffu, na0, 2);
        na1 += __shfl_xor_sync(0xffffffffu, na1, 1);
        na1 += __shfl_xor_sync(0xffffffffu, na1, 2);
        if (t == 0) {
            atomicAdd(&g_norm[(b * H_ + h) * 64 + sB3 + g],     na0);
            atomicAdd(&g_norm[(b * H_ + h) * 64 + sB3 + g + 8], na1);
        }
    }
}

__global__ void k_final(float* __restrict__ out) {
    int i = blockIdx.x * 256 + threadIdx.x;
    out[i] = g_A[i] / (g_norm[i >> 6] + 0.01f);
}

extern "C" void kernel_launch(void* const* d_in, const int* in_sizes, int n_in,
                              void* d_out, int out_size) {
    const float* x    = (const float*)d_in[0];
    const float* Wx   = (const float*)d_in[1];
    const float* bx   = (const float*)d_in[2];
    const float* Wfx  = (const float*)d_in[3];
    const float* bfx  = (const float*)d_in[4];
    const float* Wsl  = (const float*)d_in[5];
    const float* bsl  = (const float*)d_in[6];
    const float* temp = (const float*)d_in[7];
    float* out = (float*)d_out;

    cudaFuncSetAttribute(k_fused, cudaFuncAttributeMaxDynamicSharedMemorySize, SMEM_BYTES);

    k_prep<<<dim3(H_, 4), 256>>>(Wx, bx, Wsl, bsl, temp);
    k_zero<<<256, 256>>>();
    dim3 grid(NCHUNK, H_, B_);
    k_fused<<<grid, 256, SMEM_BYTES>>>(x, Wfx, bfx);
    k_final<<<256, 256>>>(out);
}